// round 15
// baseline (speedup 1.0000x reference)
#include <cuda_runtime.h>
#include <cuda_fp16.h>
#include <math.h>
#include <stdint.h>

// ---------------- problem constants ----------------
#define BATCH   4
#define CDIM    512
#define WSZ_    64
#define HW      4096
#define TTOK    16384
#define HEADDIM 64
#define HDIM    256
#define LDIM    256
#define GWIN    1024
#define SCALE   0.125f
#define SCALE_LOG2E 0.18033688011112042f   // SCALE * log2(e)

// ---------------- scratch (all half) ----------------
__device__ __half g_xt[TTOK * CDIM];               // [t][c]
__device__ __half g_pooled[BATCH * GWIN * CDIM];   // [g][c]
__device__ __half g_wt[917504];                    // transposed weights [n][k]
__device__ __half g_qkv[TTOK * 3 * HDIM];
__device__ __half g_hout[TTOK * HDIM];
__device__ __half g_lq[TTOK * LDIM];
__device__ __half g_kv[BATCH * GWIN * 2 * LDIM];
__device__ __half g_lo[TTOK * LDIM];

#define WT_QKV   0            // 768 x 512  (WT_LQ adjacent -> fused N=1024)
#define WT_LQ    393216
#define WT_LKV   524288       // 512 x 512
#define WT_HPROJ 786432       // 256 x 256
#define WT_LPROJ 851968       // 256 x 256

// ---------------- helpers ----------------
__device__ __forceinline__ uint32_t packh2(float a, float b) {
    __half2 h = __floats2half2_rn(a, b);
    return *(uint32_t*)&h;
}
__device__ __forceinline__ uint32_t exp2h2(float a, float b) {
    // pack to half2 then 2^x with one MUFU op
    uint32_t in = packh2(a, b), out;
    asm("ex2.approx.f16x2 %0, %1;" : "=r"(out) : "r"(in));
    return out;
}
__device__ __forceinline__ uint32_t smem_u32(const void* p) {
    uint32_t a;
    asm("{ .reg .u64 t; cvta.to.shared.u64 t, %1; cvt.u32.u64 %0, t; }" : "=r"(a) : "l"(p));
    return a;
}
__device__ __forceinline__ void mma_f16(float c[4], const uint32_t a[4], const uint32_t b[2]) {
    asm volatile(
        "mma.sync.aligned.m16n8k16.row.col.f32.f16.f16.f32 "
        "{%0,%1,%2,%3}, {%4,%5,%6,%7}, {%8,%9}, {%0,%1,%2,%3};\n"
        : "+f"(c[0]), "+f"(c[1]), "+f"(c[2]), "+f"(c[3])
        : "r"(a[0]), "r"(a[1]), "r"(a[2]), "r"(a[3]), "r"(b[0]), "r"(b[1]));
}
__device__ __forceinline__ void ldsm4(uint32_t r[4], uint32_t addr) {
    asm volatile("ldmatrix.sync.aligned.m8n8.x4.shared.b16 {%0,%1,%2,%3}, [%4];"
                 : "=r"(r[0]), "=r"(r[1]), "=r"(r[2]), "=r"(r[3]) : "r"(addr));
}
__device__ __forceinline__ void ldsm4t(uint32_t r[4], uint32_t addr) {
    asm volatile("ldmatrix.sync.aligned.m8n8.x4.trans.shared.b16 {%0,%1,%2,%3}, [%4];"
                 : "=r"(r[0]), "=r"(r[1]), "=r"(r[2]), "=r"(r[3]) : "r"(addr));
}
__device__ __forceinline__ void cp16(uint32_t saddr, const void* gptr) {
    asm volatile("cp.async.cg.shared.global [%0], [%1], 16;" :: "r"(saddr), "l"(gptr) : "memory");
}
#define CP_COMMIT() asm volatile("cp.async.commit_group;" ::: "memory")
#define CP_WAIT(n)  asm volatile("cp.async.wait_group %0;" :: "n"(n) : "memory")

// ---------------- transpose x (B,C,H,W) -> xt half [t][c] ----------------
__global__ void transpose_x_kernel(const float* __restrict__ x, __half* __restrict__ xt) {
    __shared__ float tile[32][33];
    int hw0 = blockIdx.x * 32;
    int c0  = blockIdx.y * 32;
    int b   = blockIdx.z;
    int tx = threadIdx.x, ty = threadIdx.y;
#pragma unroll
    for (int i = 0; i < 4; i++)
        tile[ty + i * 8][tx] = x[((size_t)(b * CDIM + c0 + ty + i * 8)) * HW + hw0 + tx];
    __syncthreads();
#pragma unroll
    for (int i = 0; i < 4; i++)
        xt[((size_t)(b * HW + hw0 + ty + i * 8)) * CDIM + c0 + tx] =
            __float2half_rn(tile[tx][ty + i * 8]);
}

// ---------------- fused weight transpose: all 5 weights -> g_wt [n][k] half ----------------
__global__ void wtrans_all_kernel(const float* __restrict__ s0, const float* __restrict__ s1,
                                  const float* __restrict__ s2, const float* __restrict__ s3,
                                  const float* __restrict__ s4, __half* __restrict__ wt) {
    __shared__ float t[32][33];
    int id = blockIdx.x;
    const float* src; __half* dst; int K, N, tix;
    if (id < 384)      { src = s0; dst = wt + WT_QKV;   K = 512; N = 768; tix = id; }
    else if (id < 512) { src = s1; dst = wt + WT_LQ;    K = 512; N = 256; tix = id - 384; }
    else if (id < 768) { src = s2; dst = wt + WT_LKV;   K = 512; N = 512; tix = id - 512; }
    else if (id < 832) { src = s3; dst = wt + WT_HPROJ; K = 256; N = 256; tix = id - 768; }
    else               { src = s4; dst = wt + WT_LPROJ; K = 256; N = 256; tix = id - 832; }
    int tilesx = K / 32;
    int k0 = (tix % tilesx) * 32, n0 = (tix / tilesx) * 32;
    int tx = threadIdx.x, ty = threadIdx.y;
#pragma unroll
    for (int i = 0; i < 4; i++)
        t[ty + i * 8][tx] = src[(size_t)(k0 + ty + i * 8) * N + n0 + tx];
    __syncthreads();
#pragma unroll
    for (int i = 0; i < 4; i++)
        dst[(size_t)(n0 + ty + i * 8) * K + k0 + tx] = __float2half_rn(t[tx][ty + i * 8]);
}

// ---------------- 2x2 average pool from xt (coalesced) -> pooled half [g][c] ----------------
__global__ void pool_kernel(const __half* __restrict__ xt, __half* __restrict__ pooled) {
    int bg = blockIdx.x;
    int b = bg >> 10;
    int g = bg & 1023;
    int gy = g >> 5, gx = g & 31;
    int t00 = b * HW + (gy * 2) * WSZ_ + gx * 2;
    const __half2* r0 = (const __half2*)(xt + (size_t)t00 * CDIM);
    const __half2* r1 = (const __half2*)(xt + (size_t)(t00 + 1) * CDIM);
    const __half2* r2 = (const __half2*)(xt + (size_t)(t00 + WSZ_) * CDIM);
    const __half2* r3 = (const __half2*)(xt + (size_t)(t00 + WSZ_ + 1) * CDIM);
    __half2* dst = (__half2*)(pooled + (size_t)bg * CDIM);
#pragma unroll
    for (int i = 0; i < 2; i++) {
        int c = threadIdx.x + i * 128;
        float2 a = __half22float2(r0[c]);
        float2 bb = __half22float2(r1[c]);
        float2 cc = __half22float2(r2[c]);
        float2 dd = __half22float2(r3[c]);
        dst[c] = __floats2half2_rn(0.25f * (a.x + bb.x + cc.x + dd.x),
                                   0.25f * (a.y + bb.y + cc.y + dd.y));
    }
}

// ---------------- GEMM core constants ----------------
#define GS_STRIDE 40
#define G_STAGE   (128 * 40)
#define MEGA_SMEM (4 * 2 * G_STAGE * 2)   // 4 stages: 81920 B
#define PROJ_SMEM 61440                   // 3 stages

// ---------------- MEGA GEMM: [qkv|lq] (1024 blocks) + kv (128 blocks), K=512, 4-stage ----
__global__ void __launch_bounds__(256, 2) h16_gemm_mega() {
    extern __shared__ char smc[];
    const uint32_t smb = smem_u32(smc);

    const int bx = blockIdx.x;
    const __half* A;
    const __half* Bt;
    int m0, n0;
    if (bx < 1024) {
        A = g_xt; Bt = g_wt + WT_QKV;
        m0 = (bx >> 3) * 128; n0 = (bx & 7) * 128;
    } else {
        int t = bx - 1024;
        A = g_pooled; Bt = g_wt + WT_LKV;
        m0 = (t >> 2) * 128; n0 = (t & 3) * 128;
    }
    const int K = 512;

    const int tid = threadIdx.x;
    const int warp = tid >> 5, lane = tid & 31;
    const int g = lane >> 2, tig = lane & 3;
    const int mw = (warp & 1) * 64, nw = (warp >> 1) * 32;

    float acc[4][4][4];
#pragma unroll
    for (int mt = 0; mt < 4; mt++)
#pragma unroll
        for (int nt = 0; nt < 4; nt++)
#pragma unroll
            for (int j = 0; j < 4; j++) acc[mt][nt][j] = 0.f;

    auto fill = [&](int stage, int k0) {
        uint32_t abase = smb + (uint32_t)(stage * 2 * G_STAGE) * 2;
        uint32_t bbase = abase + G_STAGE * 2;
#pragma unroll
        for (int i = 0; i < 2; i++) {
            int id = tid + i * 256;
            int r = id >> 2, c = (id & 3) * 8;
            cp16(abase + (r * GS_STRIDE + c) * 2, &A[(size_t)(m0 + r) * K + k0 + c]);
            cp16(bbase + (r * GS_STRIDE + c) * 2, &Bt[(size_t)(n0 + r) * K + k0 + c]);
        }
    };

    const int nIter = K / 32;   // 16
    fill(0, 0); CP_COMMIT();
    fill(1, 32); CP_COMMIT();
    fill(2, 64); CP_COMMIT();

    for (int it = 0; it < nIter; it++) {
        CP_WAIT(2);
        __syncthreads();
        int stage = it & 3;
        uint32_t abase = smb + (uint32_t)(stage * 2 * G_STAGE) * 2;
        uint32_t bbase = abase + G_STAGE * 2;
#pragma unroll
        for (int ks = 0; ks < 2; ks++) {
            uint32_t af[4][4], bf[4][2];
#pragma unroll
            for (int mt = 0; mt < 4; mt++) {
                uint32_t addr = abase +
                    ((mw + mt * 16 + (lane & 15)) * GS_STRIDE + ks * 16 + (lane >> 4) * 8) * 2;
                ldsm4(af[mt], addr);
            }
#pragma unroll
            for (int np = 0; np < 2; np++) {
                uint32_t r4[4];
                uint32_t addr = bbase +
                    ((nw + np * 16 + (lane & 7) + (lane >> 4) * 8) * GS_STRIDE +
                     ks * 16 + ((lane >> 3) & 1) * 8) * 2;
                ldsm4(r4, addr);
                bf[2 * np][0] = r4[0]; bf[2 * np][1] = r4[1];
                bf[2 * np + 1][0] = r4[2]; bf[2 * np + 1][1] = r4[3];
            }
#pragma unroll
            for (int mt = 0; mt < 4; mt++)
#pragma unroll
                for (int nt = 0; nt < 4; nt++)
                    mma_f16(acc[mt][nt], af[mt], bf[nt]);
        }
        if (it + 3 < nIter) fill((it + 3) & 3, (it + 3) * 32);
        CP_COMMIT();
    }

    __half* C; int Ncols, col0;
    if (bx < 1024) {
        if (n0 < 768) { C = g_qkv; Ncols = 768; col0 = n0; }
        else          { C = g_lq;  Ncols = 256; col0 = n0 - 768; }
    } else {
        C = g_kv; Ncols = 512; col0 = n0;
    }
#pragma unroll
    for (int mt = 0; mt < 4; mt++) {
        int r = m0 + mw + mt * 16 + g;
#pragma unroll
        for (int nt = 0; nt < 4; nt++) {
            int c = col0 + nw + nt * 8 + tig * 2;
            *(uint32_t*)&C[(size_t)r * Ncols + c] = packh2(acc[mt][nt][0], acc[mt][nt][1]);
            *(uint32_t*)&C[(size_t)(r + 8) * Ncols + c] = packh2(acc[mt][nt][2], acc[mt][nt][3]);
        }
    }
}

// ---------------- proj GEMM (TOUT): z=0 hifi, z=1 lofi, K=256, 3-stage ----------------
__global__ void __launch_bounds__(256, 2) h16_gemm_proj(const float* __restrict__ h_proj_b,
                                                        const float* __restrict__ l_proj_b,
                                                        float* __restrict__ out) {
    extern __shared__ char smc[];
    const uint32_t smb = smem_u32(smc);

    const __half* A;
    const __half* Bt;
    const float* bias;
    int cbase;
    if (blockIdx.z == 0) { A = g_hout; Bt = g_wt + WT_HPROJ; bias = h_proj_b; cbase = 0; }
    else                 { A = g_lo;   Bt = g_wt + WT_LPROJ; bias = l_proj_b; cbase = 256; }
    const int K = 256;

    const int tid = threadIdx.x;
    const int warp = tid >> 5, lane = tid & 31;
    const int g = lane >> 2, tig = lane & 3;
    const int mw = (warp & 1) * 64, nw = (warp >> 1) * 32;
    const int m0 = blockIdx.y * 128, n0 = blockIdx.x * 128;

    float acc[4][4][4];
#pragma unroll
    for (int mt = 0; mt < 4; mt++)
#pragma unroll
        for (int nt = 0; nt < 4; nt++)
#pragma unroll
            for (int j = 0; j < 4; j++) acc[mt][nt][j] = 0.f;

    auto fill = [&](int stage, int k0) {
        uint32_t abase = smb + (uint32_t)(stage * 2 * G_STAGE) * 2;
        uint32_t bbase = abase + G_STAGE * 2;
#pragma unroll
        for (int i = 0; i < 2; i++) {
            int id = tid + i * 256;
            int r = id >> 2, c = (id & 3) * 8;
            cp16(abase + (r * GS_STRIDE + c) * 2, &A[(size_t)(m0 + r) * K + k0 + c]);
            cp16(bbase + (r * GS_STRIDE + c) * 2, &Bt[(size_t)(n0 + r) * K + k0 + c]);
        }
    };

    const int nIter = K / 32;   // 8
    fill(0, 0); CP_COMMIT();
    fill(1, 32); CP_COMMIT();

    for (int it = 0; it < nIter; it++) {
        CP_WAIT(1);
        __syncthreads();
        int stage = it % 3;
        uint32_t abase = smb + (uint32_t)(stage * 2 * G_STAGE) * 2;
        uint32_t bbase = abase + G_STAGE * 2;
#pragma unroll
        for (int ks = 0; ks < 2; ks++) {
            uint32_t af[4][4], bf[4][2];
#pragma unroll
            for (int mt = 0; mt < 4; mt++) {
                uint32_t addr = abase +
                    ((mw + mt * 16 + (lane & 15)) * GS_STRIDE + ks * 16 + (lane >> 4) * 8) * 2;
                ldsm4(af[mt], addr);
            }
#pragma unroll
            for (int np = 0; np < 2; np++) {
                uint32_t r4[4];
                uint32_t addr = bbase +
                    ((nw + np * 16 + (lane & 7) + (lane >> 4) * 8) * GS_STRIDE +
                     ks * 16 + ((lane >> 3) & 1) * 8) * 2;
                ldsm4(r4, addr);
                bf[2 * np][0] = r4[0]; bf[2 * np][1] = r4[1];
                bf[2 * np + 1][0] = r4[2]; bf[2 * np + 1][1] = r4[3];
            }
#pragma unroll
            for (int mt = 0; mt < 4; mt++)
#pragma unroll
                for (int nt = 0; nt < 4; nt++)
                    mma_f16(acc[mt][nt], af[mt], bf[nt]);
        }
        if (it + 2 < nIter) fill((it + 2) % 3, (it + 2) * 32);
        CP_COMMIT();
    }

    __syncthreads();
    float* stg = (float*)smc;
    const int bq = m0 / HW, hw0 = m0 % HW;
#pragma unroll
    for (int h = 0; h < 2; h++) {
        if (h) __syncthreads();
        if ((nw >> 6) == h) {
#pragma unroll
            for (int mt = 0; mt < 4; mt++)
#pragma unroll
                for (int nt = 0; nt < 4; nt++) {
                    int cl = nw + nt * 8 + tig * 2;
                    int rl = mw + mt * 16 + g;
                    float b0 = bias[n0 + cl], b1 = bias[n0 + cl + 1];
                    int cs = cl - h * 64;
                    stg[cs * 132 + rl]           = acc[mt][nt][0] + b0;
                    stg[(cs + 1) * 132 + rl]     = acc[mt][nt][1] + b1;
                    stg[cs * 132 + rl + 8]       = acc[mt][nt][2] + b0;
                    stg[(cs + 1) * 132 + rl + 8] = acc[mt][nt][3] + b1;
                }
        }
        __syncthreads();
#pragma unroll
        for (int i = 0; i < 8; i++) {
            int lin = tid + i * 256;
            int c = lin >> 5, m4 = (lin & 31) * 4;
            float4 v = *(const float4*)&stg[c * 132 + m4];
            *(float4*)&out[((size_t)(bq * CDIM + cbase + n0 + h * 64 + c)) * HW + hw0 + m4] = v;
        }
    }
}

// ---------------- window attention (no-max softmax; 2 windows/block) ----------------
__global__ void winattn_kernel(const __half* __restrict__ qkv, __half* __restrict__ hout) {
    int win = blockIdx.x * 2 + (threadIdx.x >> 7);
    int b = win >> 10;
    int g = win & 1023;
    int gy = g >> 5, gx = g & 31;
    int head = (threadIdx.x >> 5) & 3;
    int lane = threadIdx.x & 31;

    int tbase = b * HW + gy * 2 * WSZ_ + gx * 2;
    int t[4] = {tbase, tbase + 1, tbase + WSZ_, tbase + WSZ_ + 1};

    float2 q[4], k[4], v[4];
#pragma unroll
    for (int n = 0; n < 4; n++) {
        const __half* row = qkv + (size_t)t[n] * (3 * HDIM) + head * HEADDIM + 2 * lane;
        q[n] = __half22float2(*(const __half2*)&row[0]);
        k[n] = __half22float2(*(const __half2*)&row[HDIM]);
        v[n] = __half22float2(*(const __half2*)&row[2 * HDIM]);
    }

    float s[4][4];
#pragma unroll
    for (int n = 0; n < 4; n++)
#pragma unroll
        for (int m = 0; m < 4; m++) s[n][m] = q[n].x * k[m].x + q[n].y * k[m].y;

#pragma unroll
    for (int o = 16; o > 0; o >>= 1)
#pragma unroll
        for (int n = 0; n < 4; n++)
#pragma unroll
            for (int m = 0; m < 4; m++) s[n][m] += __shfl_xor_sync(0xffffffffu, s[n][m], o);

#pragma unroll
    for (int n = 0; n < 4; n++) {
        float p[4], l = 0.f;
#pragma unroll
        for (int m = 0; m < 4; m++) { p[m] = __expf(s[n][m] * SCALE); l += p[m]; }
        float inv = 1.f / l;
        float ox = 0.f, oy = 0.f;
#pragma unroll
        for (int m = 0; m < 4; m++) { ox += p[m] * v[m].x; oy += p[m] * v[m].y; }
        *(__half2*)&hout[(size_t)t[n] * HDIM + head * HEADDIM + 2 * lane] =
            __floats2half2_rn(ox * inv, oy * inv);
    }
}

// ---------------- low-freq flash attention: ex2.f16x2 + ones-mma row sums ----
#define LQH 0
#define LKH 9216
#define LVH 18432
#define LPH 27648
#define KVSTG 4608
#define LA_SMEM 73728
#define ONES_H2 0x3C003C00u

__global__ void __launch_bounds__(256, 2) lowattn_h16_kernel(const __half* __restrict__ lq,
                                                             const __half* __restrict__ kv,
                                                             __half* __restrict__ lo) {
    extern __shared__ char smc[];
    const uint32_t smb = smem_u32(smc);
    uint32_t* smu = (uint32_t*)smc;

    int q0 = blockIdx.x * 128;
    int bh = blockIdx.y;
    int b = bh >> 2, head = bh & 3;
    int tid = threadIdx.x;
    int warp = tid >> 5, lane = tid & 31;
    int g = lane >> 2, tig = lane & 3;
    int rbase = warp * 16;

    auto fill_kv = [&](int chunk) {
        int s = chunk & 1;
        uint32_t kb = smb + (LKH + s * KVSTG) * 2;
        uint32_t vb = smb + (LVH + s * KVSTG) * 2;
#pragma unroll
        for (int i = 0; i < 2; i++) {
            int id = tid + i * 256;
            int r = id >> 3, c = (id & 7) * 8;
            const __half* src = kv + (size_t)(b * GWIN + chunk * 64 + r) * (2 * LDIM)
                                + head * HEADDIM + c;
            cp16(kb + (r * 72 + c) * 2, src);
            cp16(vb + (r * 72 + c) * 2, src + LDIM);
        }
    };

    {
        uint32_t qb = smb + LQH * 2;
#pragma unroll
        for (int i = 0; i < 4; i++) {
            int id = tid + i * 256;
            int r = id >> 3, c = (id & 7) * 8;
            cp16(qb + (r * 72 + c) * 2,
                 &lq[(size_t)(b * HW + q0 + r) * LDIM + head * HEADDIM + c]);
        }
        fill_kv(0);
        CP_COMMIT();
    }

    float O[8][4];
#pragma unroll
    for (int nt = 0; nt < 8; nt++)
#pragma unroll
        for (int j = 0; j < 4; j++) O[nt][j] = 0.f;
    float Lacc[4] = {0.f, 0.f, 0.f, 0.f};   // ones-mma row sums
    const uint32_t ones_bf[2] = { ONES_H2, ONES_H2 };

    uint32_t af_q[4][4];   // Q fragments, loaded once at t==0

    for (int t = 0; t < 16; t++) {
        if (t + 1 < 16) fill_kv(t + 1);
        CP_COMMIT();
        CP_WAIT(1);
        __syncthreads();
        int s = t & 1;
        uint32_t kbase = smb + (LKH + s * KVSTG) * 2;
        uint32_t vbase = smb + (LVH + s * KVSTG) * 2;
        uint32_t pbase = smb + LPH * 2;

        if (t == 0) {
            uint32_t qbase = smb + LQH * 2;
#pragma unroll
            for (int ks = 0; ks < 4; ks++)
                ldsm4(af_q[ks],
                      qbase + ((rbase + (lane & 15)) * 72 + ks * 16 + (lane >> 4) * 8) * 2);
        }

        float S[8][4];
#pragma unroll
        for (int nt = 0; nt < 8; nt++)
#pragma unroll
            for (int j = 0; j < 4; j++) S[nt][j] = 0.f;

#pragma unroll
        for (int ks = 0; ks < 4; ks++) {
#pragma unroll
            for (int np = 0; np < 4; np++) {
                uint32_t r4[4];
                uint32_t addr = kbase +
                    ((np * 16 + (lane & 7) + (lane >> 4) * 8) * 72 +
                     ks * 16 + ((lane >> 3) & 1) * 8) * 2;
                ldsm4(r4, addr);
                uint32_t bf0[2] = { r4[0], r4[1] };
                uint32_t bf1[2] = { r4[2], r4[3] };
                mma_f16(S[2 * np], af_q[ks], bf0);
                mma_f16(S[2 * np + 1], af_q[ks], bf1);
            }
        }

        // P = 2^(S * SCALE * log2e) via one MUFU per two values; store as half2
        int r = rbase + g;
#pragma unroll
        for (int nt = 0; nt < 8; nt++) {
            smu[(LPH >> 1) + r * 36 + nt * 4 + tig] =
                exp2h2(S[nt][0] * SCALE_LOG2E, S[nt][1] * SCALE_LOG2E);
            smu[(LPH >> 1) + (r + 8) * 36 + nt * 4 + tig] =
                exp2h2(S[nt][2] * SCALE_LOG2E, S[nt][3] * SCALE_LOG2E);
        }
        __syncwarp();

        // O += P @ V ; L += P @ ones (row sums on the tensor pipe)
#pragma unroll
        for (int ks = 0; ks < 4; ks++) {
            uint32_t af[4];
            ldsm4(af, pbase + ((rbase + (lane & 15)) * 72 + ks * 16 + (lane >> 4) * 8) * 2);
            mma_f16(Lacc, af, ones_bf);
#pragma unroll
            for (int np = 0; np < 4; np++) {
                uint32_t r4[4];
                uint32_t addr = vbase +
                    ((ks * 16 + (lane & 15)) * 72 + np * 16 + (lane >> 4) * 8) * 2;
                ldsm4t(r4, addr);
                uint32_t bf0[2] = { r4[0], r4[1] };
                uint32_t bf1[2] = { r4[2], r4[3] };
                mma_f16(O[2 * np], af, bf0);
                mma_f16(O[2 * np + 1], af, bf1);
            }
        }
        __syncthreads();
    }

    float inv0 = 1.f / Lacc[0], inv1 = 1.f / Lacc[2];
    int r = q0 + rbase + g;
#pragma unroll
    for (int nt = 0; nt < 8; nt++) {
        int c = head * HEADDIM + nt * 8 + tig * 2;
        *(uint32_t*)&lo[(size_t)(b * HW + r) * LDIM + c] = packh2(O[nt][0] * inv0, O[nt][1] * inv0);
        *(uint32_t*)&lo[(size_t)(b * HW + r + 8) * LDIM + c] = packh2(O[nt][2] * inv1, O[nt][3] * inv1);
    }
}

// ---------------- launch ----------------
extern "C" void kernel_launch(void* const* d_in, const int* in_sizes, int n_in,
                              void* d_out, int out_size) {
    const float* x        = (const float*)d_in[0];
    const float* h_qkv_w  = (const float*)d_in[1];
    const float* h_proj_w = (const float*)d_in[2];
    const float* h_proj_b = (const float*)d_in[3];
    const float* l_q_w    = (const float*)d_in[4];
    const float* l_kv_w   = (const float*)d_in[5];
    const float* l_proj_w = (const float*)d_in[6];
    const float* l_proj_b = (const float*)d_in[7];
    float* out = (float*)d_out;

    __half *p_xt, *p_pooled, *p_wt, *p_qkv, *p_hout, *p_lq, *p_kv, *p_lo;
    cudaGetSymbolAddress((void**)&p_xt, g_xt);
    cudaGetSymbolAddress((void**)&p_pooled, g_pooled);
    cudaGetSymbolAddress((void**)&p_wt, g_wt);
    cudaGetSymbolAddress((void**)&p_qkv, g_qkv);
    cudaGetSymbolAddress((void**)&p_hout, g_hout);
    cudaGetSymbolAddress((void**)&p_lq, g_lq);
    cudaGetSymbolAddress((void**)&p_kv, g_kv);
    cudaGetSymbolAddress((void**)&p_lo, g_lo);

    cudaFuncSetAttribute(h16_gemm_mega,
                         cudaFuncAttributeMaxDynamicSharedMemorySize, MEGA_SMEM);
    cudaFuncSetAttribute(h16_gemm_proj,
                         cudaFuncAttributeMaxDynamicSharedMemorySize, PROJ_SMEM);
    cudaFuncSetAttribute(lowattn_h16_kernel,
                         cudaFuncAttributeMaxDynamicSharedMemorySize, LA_SMEM);

    // 0) layout prep
    transpose_x_kernel<<<dim3(HW / 32, CDIM / 32, BATCH), dim3(32, 8)>>>(x, p_xt);
    wtrans_all_kernel<<<896, dim3(32, 8)>>>(h_qkv_w, l_q_w, l_kv_w, h_proj_w, l_proj_w, p_wt);
    // 1) pool
    pool_kernel<<<BATCH * GWIN, 128>>>(p_xt, p_pooled);
    // 2) MEGA: [qkv|lq] (1024 blocks) + kv (128 blocks)
    h16_gemm_mega<<<1152, 256, MEGA_SMEM>>>();
    // 3) window attention
    winattn_kernel<<<BATCH * GWIN / 2, 256>>>(p_qkv, p_hout);
    // 4) low-freq flash attention
    lowattn_h16_kernel<<<dim3(HW / 128, BATCH * 4), 256, LA_SMEM>>>(p_lq, p_kv, p_lo);
    // 5) fused projections
    h16_gemm_proj<<<dim3(HDIM / 128, TTOK / 128, 2), 256, PROJ_SMEM>>>(h_proj_b, l_proj_b, out);
}

// round 16
// speedup vs baseline: 1.0604x; 1.0604x over previous
#include <cuda_runtime.h>
#include <cuda_fp16.h>
#include <math.h>
#include <stdint.h>

// ---------------- problem constants ----------------
#define BATCH   4
#define CDIM    512
#define WSZ_    64
#define HW      4096
#define TTOK    16384
#define HEADDIM 64
#define HDIM    256
#define LDIM    256
#define GWIN    1024
#define SCALE   0.125f
#define SCALE_LOG2E 0.18033688011112042f   // SCALE * log2(e)

// ---------------- scratch (all half) ----------------
__device__ __half g_xt[TTOK * CDIM];               // [t][c]
__device__ __half g_pooled[BATCH * GWIN * CDIM];   // [g][c]
__device__ __half g_wt[917504];                    // transposed weights [n][k]
__device__ __half g_qkv[TTOK * 3 * HDIM];
__device__ __half g_hout[TTOK * HDIM];
__device__ __half g_lq[TTOK * LDIM];
__device__ __half g_kv[BATCH * GWIN * 2 * LDIM];
__device__ __half g_lo[TTOK * LDIM];

#define WT_QKV   0            // 768 x 512  (WT_LQ adjacent -> fused N=1024)
#define WT_LQ    393216
#define WT_LKV   524288       // 512 x 512
#define WT_HPROJ 786432       // 256 x 256
#define WT_LPROJ 851968       // 256 x 256

// ---------------- helpers ----------------
__device__ __forceinline__ uint32_t packh2(float a, float b) {
    __half2 h = __floats2half2_rn(a, b);
    return *(uint32_t*)&h;
}
__device__ __forceinline__ uint32_t exp2h2(float a, float b) {
    uint32_t in = packh2(a, b), out;
    asm("ex2.approx.f16x2 %0, %1;" : "=r"(out) : "r"(in));
    return out;
}
__device__ __forceinline__ uint32_t smem_u32(const void* p) {
    uint32_t a;
    asm("{ .reg .u64 t; cvta.to.shared.u64 t, %1; cvt.u32.u64 %0, t; }" : "=r"(a) : "l"(p));
    return a;
}
__device__ __forceinline__ void mma_f16(float c[4], const uint32_t a[4], const uint32_t b[2]) {
    asm volatile(
        "mma.sync.aligned.m16n8k16.row.col.f32.f16.f16.f32 "
        "{%0,%1,%2,%3}, {%4,%5,%6,%7}, {%8,%9}, {%0,%1,%2,%3};\n"
        : "+f"(c[0]), "+f"(c[1]), "+f"(c[2]), "+f"(c[3])
        : "r"(a[0]), "r"(a[1]), "r"(a[2]), "r"(a[3]), "r"(b[0]), "r"(b[1]));
}
__device__ __forceinline__ void ldsm4(uint32_t r[4], uint32_t addr) {
    asm volatile("ldmatrix.sync.aligned.m8n8.x4.shared.b16 {%0,%1,%2,%3}, [%4];"
                 : "=r"(r[0]), "=r"(r[1]), "=r"(r[2]), "=r"(r[3]) : "r"(addr));
}
__device__ __forceinline__ void ldsm4t(uint32_t r[4], uint32_t addr) {
    asm volatile("ldmatrix.sync.aligned.m8n8.x4.trans.shared.b16 {%0,%1,%2,%3}, [%4];"
                 : "=r"(r[0]), "=r"(r[1]), "=r"(r[2]), "=r"(r[3]) : "r"(addr));
}
__device__ __forceinline__ void cp16(uint32_t saddr, const void* gptr) {
    asm volatile("cp.async.cg.shared.global [%0], [%1], 16;" :: "r"(saddr), "l"(gptr) : "memory");
}
#define CP_COMMIT() asm volatile("cp.async.commit_group;" ::: "memory")
#define CP_WAIT(n)  asm volatile("cp.async.wait_group %0;" :: "n"(n) : "memory")

// ---------------- transpose x (B,C,H,W) -> xt half [t][c] ----------------
__global__ void transpose_x_kernel(const float* __restrict__ x, __half* __restrict__ xt) {
    __shared__ float tile[32][33];
    int hw0 = blockIdx.x * 32;
    int c0  = blockIdx.y * 32;
    int b   = blockIdx.z;
    int tx = threadIdx.x, ty = threadIdx.y;
#pragma unroll
    for (int i = 0; i < 4; i++)
        tile[ty + i * 8][tx] = x[((size_t)(b * CDIM + c0 + ty + i * 8)) * HW + hw0 + tx];
    __syncthreads();
#pragma unroll
    for (int i = 0; i < 4; i++)
        xt[((size_t)(b * HW + hw0 + ty + i * 8)) * CDIM + c0 + tx] =
            __float2half_rn(tile[tx][ty + i * 8]);
}

// ---------------- fused weight transpose: all 5 weights -> g_wt [n][k] half ----------------
__global__ void wtrans_all_kernel(const float* __restrict__ s0, const float* __restrict__ s1,
                                  const float* __restrict__ s2, const float* __restrict__ s3,
                                  const float* __restrict__ s4, __half* __restrict__ wt) {
    __shared__ float t[32][33];
    int id = blockIdx.x;
    const float* src; __half* dst; int K, N, tix;
    if (id < 384)      { src = s0; dst = wt + WT_QKV;   K = 512; N = 768; tix = id; }
    else if (id < 512) { src = s1; dst = wt + WT_LQ;    K = 512; N = 256; tix = id - 384; }
    else if (id < 768) { src = s2; dst = wt + WT_LKV;   K = 512; N = 512; tix = id - 512; }
    else if (id < 832) { src = s3; dst = wt + WT_HPROJ; K = 256; N = 256; tix = id - 768; }
    else               { src = s4; dst = wt + WT_LPROJ; K = 256; N = 256; tix = id - 832; }
    int tilesx = K / 32;
    int k0 = (tix % tilesx) * 32, n0 = (tix / tilesx) * 32;
    int tx = threadIdx.x, ty = threadIdx.y;
#pragma unroll
    for (int i = 0; i < 4; i++)
        t[ty + i * 8][tx] = src[(size_t)(k0 + ty + i * 8) * N + n0 + tx];
    __syncthreads();
#pragma unroll
    for (int i = 0; i < 4; i++)
        dst[(size_t)(n0 + ty + i * 8) * K + k0 + tx] = __float2half_rn(t[tx][ty + i * 8]);
}

// ---------------- 2x2 average pool from xt (coalesced) -> pooled half [g][c] ----------------
__global__ void pool_kernel(const __half* __restrict__ xt, __half* __restrict__ pooled) {
    int bg = blockIdx.x;
    int b = bg >> 10;
    int g = bg & 1023;
    int gy = g >> 5, gx = g & 31;
    int t00 = b * HW + (gy * 2) * WSZ_ + gx * 2;
    const __half2* r0 = (const __half2*)(xt + (size_t)t00 * CDIM);
    const __half2* r1 = (const __half2*)(xt + (size_t)(t00 + 1) * CDIM);
    const __half2* r2 = (const __half2*)(xt + (size_t)(t00 + WSZ_) * CDIM);
    const __half2* r3 = (const __half2*)(xt + (size_t)(t00 + WSZ_ + 1) * CDIM);
    __half2* dst = (__half2*)(pooled + (size_t)bg * CDIM);
#pragma unroll
    for (int i = 0; i < 2; i++) {
        int c = threadIdx.x + i * 128;
        float2 a = __half22float2(r0[c]);
        float2 bb = __half22float2(r1[c]);
        float2 cc = __half22float2(r2[c]);
        float2 dd = __half22float2(r3[c]);
        dst[c] = __floats2half2_rn(0.25f * (a.x + bb.x + cc.x + dd.x),
                                   0.25f * (a.y + bb.y + cc.y + dd.y));
    }
}

// ---------------- GEMM core constants ----------------
#define GS_STRIDE 40
#define G_STAGE   (128 * 40)
#define H16_SMEM  61440                   // 3 stages

// ---------------- MEGA GEMM: [qkv|lq] (1024 blocks) + kv (128 blocks), K=512, 3-stage ----
__global__ void __launch_bounds__(256, 2) h16_gemm_mega() {
    extern __shared__ char smc[];
    const uint32_t smb = smem_u32(smc);

    const int bx = blockIdx.x;
    const __half* A;
    const __half* Bt;
    int m0, n0;
    if (bx < 1024) {
        A = g_xt; Bt = g_wt + WT_QKV;
        m0 = (bx >> 3) * 128; n0 = (bx & 7) * 128;
    } else {
        int t = bx - 1024;
        A = g_pooled; Bt = g_wt + WT_LKV;
        m0 = (t >> 2) * 128; n0 = (t & 3) * 128;
    }
    const int K = 512;

    const int tid = threadIdx.x;
    const int warp = tid >> 5, lane = tid & 31;
    const int g = lane >> 2, tig = lane & 3;
    const int mw = (warp & 1) * 64, nw = (warp >> 1) * 32;

    float acc[4][4][4];
#pragma unroll
    for (int mt = 0; mt < 4; mt++)
#pragma unroll
        for (int nt = 0; nt < 4; nt++)
#pragma unroll
            for (int j = 0; j < 4; j++) acc[mt][nt][j] = 0.f;

    auto fill = [&](int stage, int k0) {
        uint32_t abase = smb + (uint32_t)(stage * 2 * G_STAGE) * 2;
        uint32_t bbase = abase + G_STAGE * 2;
#pragma unroll
        for (int i = 0; i < 2; i++) {
            int id = tid + i * 256;
            int r = id >> 2, c = (id & 3) * 8;
            cp16(abase + (r * GS_STRIDE + c) * 2, &A[(size_t)(m0 + r) * K + k0 + c]);
            cp16(bbase + (r * GS_STRIDE + c) * 2, &Bt[(size_t)(n0 + r) * K + k0 + c]);
        }
    };

    const int nIter = K / 32;   // 16
    fill(0, 0); CP_COMMIT();
    fill(1, 32); CP_COMMIT();

    for (int it = 0; it < nIter; it++) {
        CP_WAIT(1);
        __syncthreads();
        int stage = it % 3;
        uint32_t abase = smb + (uint32_t)(stage * 2 * G_STAGE) * 2;
        uint32_t bbase = abase + G_STAGE * 2;
#pragma unroll
        for (int ks = 0; ks < 2; ks++) {
            uint32_t af[4][4], bf[4][2];
#pragma unroll
            for (int mt = 0; mt < 4; mt++) {
                uint32_t addr = abase +
                    ((mw + mt * 16 + (lane & 15)) * GS_STRIDE + ks * 16 + (lane >> 4) * 8) * 2;
                ldsm4(af[mt], addr);
            }
#pragma unroll
            for (int np = 0; np < 2; np++) {
                uint32_t r4[4];
                uint32_t addr = bbase +
                    ((nw + np * 16 + (lane & 7) + (lane >> 4) * 8) * GS_STRIDE +
                     ks * 16 + ((lane >> 3) & 1) * 8) * 2;
                ldsm4(r4, addr);
                bf[2 * np][0] = r4[0]; bf[2 * np][1] = r4[1];
                bf[2 * np + 1][0] = r4[2]; bf[2 * np + 1][1] = r4[3];
            }
#pragma unroll
            for (int mt = 0; mt < 4; mt++)
#pragma unroll
                for (int nt = 0; nt < 4; nt++)
                    mma_f16(acc[mt][nt], af[mt], bf[nt]);
        }
        if (it + 2 < nIter) fill((it + 2) % 3, (it + 2) * 32);
        CP_COMMIT();
    }

    __half* C; int Ncols, col0;
    if (bx < 1024) {
        if (n0 < 768) { C = g_qkv; Ncols = 768; col0 = n0; }
        else          { C = g_lq;  Ncols = 256; col0 = n0 - 768; }
    } else {
        C = g_kv; Ncols = 512; col0 = n0;
    }
#pragma unroll
    for (int mt = 0; mt < 4; mt++) {
        int r = m0 + mw + mt * 16 + g;
#pragma unroll
        for (int nt = 0; nt < 4; nt++) {
            int c = col0 + nw + nt * 8 + tig * 2;
            *(uint32_t*)&C[(size_t)r * Ncols + c] = packh2(acc[mt][nt][0], acc[mt][nt][1]);
            *(uint32_t*)&C[(size_t)(r + 8) * Ncols + c] = packh2(acc[mt][nt][2], acc[mt][nt][3]);
        }
    }
}

// ---------------- proj GEMM (TOUT): z=0 hifi, z=1 lofi, K=256, 3-stage ----------------
__global__ void __launch_bounds__(256, 2) h16_gemm_proj(const float* __restrict__ h_proj_b,
                                                        const float* __restrict__ l_proj_b,
                                                        float* __restrict__ out) {
    extern __shared__ char smc[];
    const uint32_t smb = smem_u32(smc);

    const __half* A;
    const __half* Bt;
    const float* bias;
    int cbase;
    if (blockIdx.z == 0) { A = g_hout; Bt = g_wt + WT_HPROJ; bias = h_proj_b; cbase = 0; }
    else                 { A = g_lo;   Bt = g_wt + WT_LPROJ; bias = l_proj_b; cbase = 256; }
    const int K = 256;

    const int tid = threadIdx.x;
    const int warp = tid >> 5, lane = tid & 31;
    const int g = lane >> 2, tig = lane & 3;
    const int mw = (warp & 1) * 64, nw = (warp >> 1) * 32;
    const int m0 = blockIdx.y * 128, n0 = blockIdx.x * 128;

    float acc[4][4][4];
#pragma unroll
    for (int mt = 0; mt < 4; mt++)
#pragma unroll
        for (int nt = 0; nt < 4; nt++)
#pragma unroll
            for (int j = 0; j < 4; j++) acc[mt][nt][j] = 0.f;

    auto fill = [&](int stage, int k0) {
        uint32_t abase = smb + (uint32_t)(stage * 2 * G_STAGE) * 2;
        uint32_t bbase = abase + G_STAGE * 2;
#pragma unroll
        for (int i = 0; i < 2; i++) {
            int id = tid + i * 256;
            int r = id >> 2, c = (id & 3) * 8;
            cp16(abase + (r * GS_STRIDE + c) * 2, &A[(size_t)(m0 + r) * K + k0 + c]);
            cp16(bbase + (r * GS_STRIDE + c) * 2, &Bt[(size_t)(n0 + r) * K + k0 + c]);
        }
    };

    const int nIter = K / 32;   // 8
    fill(0, 0); CP_COMMIT();
    fill(1, 32); CP_COMMIT();

    for (int it = 0; it < nIter; it++) {
        CP_WAIT(1);
        __syncthreads();
        int stage = it % 3;
        uint32_t abase = smb + (uint32_t)(stage * 2 * G_STAGE) * 2;
        uint32_t bbase = abase + G_STAGE * 2;
#pragma unroll
        for (int ks = 0; ks < 2; ks++) {
            uint32_t af[4][4], bf[4][2];
#pragma unroll
            for (int mt = 0; mt < 4; mt++) {
                uint32_t addr = abase +
                    ((mw + mt * 16 + (lane & 15)) * GS_STRIDE + ks * 16 + (lane >> 4) * 8) * 2;
                ldsm4(af[mt], addr);
            }
#pragma unroll
            for (int np = 0; np < 2; np++) {
                uint32_t r4[4];
                uint32_t addr = bbase +
                    ((nw + np * 16 + (lane & 7) + (lane >> 4) * 8) * GS_STRIDE +
                     ks * 16 + ((lane >> 3) & 1) * 8) * 2;
                ldsm4(r4, addr);
                bf[2 * np][0] = r4[0]; bf[2 * np][1] = r4[1];
                bf[2 * np + 1][0] = r4[2]; bf[2 * np + 1][1] = r4[3];
            }
#pragma unroll
            for (int mt = 0; mt < 4; mt++)
#pragma unroll
                for (int nt = 0; nt < 4; nt++)
                    mma_f16(acc[mt][nt], af[mt], bf[nt]);
        }
        if (it + 2 < nIter) fill((it + 2) % 3, (it + 2) * 32);
        CP_COMMIT();
    }

    __syncthreads();
    float* stg = (float*)smc;
    const int bq = m0 / HW, hw0 = m0 % HW;
#pragma unroll
    for (int h = 0; h < 2; h++) {
        if (h) __syncthreads();
        if ((nw >> 6) == h) {
#pragma unroll
            for (int mt = 0; mt < 4; mt++)
#pragma unroll
                for (int nt = 0; nt < 4; nt++) {
                    int cl = nw + nt * 8 + tig * 2;
                    int rl = mw + mt * 16 + g;
                    float b0 = bias[n0 + cl], b1 = bias[n0 + cl + 1];
                    int cs = cl - h * 64;
                    stg[cs * 132 + rl]           = acc[mt][nt][0] + b0;
                    stg[(cs + 1) * 132 + rl]     = acc[mt][nt][1] + b1;
                    stg[cs * 132 + rl + 8]       = acc[mt][nt][2] + b0;
                    stg[(cs + 1) * 132 + rl + 8] = acc[mt][nt][3] + b1;
                }
        }
        __syncthreads();
#pragma unroll
        for (int i = 0; i < 8; i++) {
            int lin = tid + i * 256;
            int c = lin >> 5, m4 = (lin & 31) * 4;
            float4 v = *(const float4*)&stg[c * 132 + m4];
            *(float4*)&out[((size_t)(bq * CDIM + cbase + n0 + h * 64 + c)) * HW + hw0 + m4] = v;
        }
    }
}

// ---------------- window attention (no-max softmax; 2 windows/block) ----------------
__global__ void winattn_kernel(const __half* __restrict__ qkv, __half* __restrict__ hout) {
    int win = blockIdx.x * 2 + (threadIdx.x >> 7);
    int b = win >> 10;
    int g = win & 1023;
    int gy = g >> 5, gx = g & 31;
    int head = (threadIdx.x >> 5) & 3;
    int lane = threadIdx.x & 31;

    int tbase = b * HW + gy * 2 * WSZ_ + gx * 2;
    int t[4] = {tbase, tbase + 1, tbase + WSZ_, tbase + WSZ_ + 1};

    float2 q[4], k[4], v[4];
#pragma unroll
    for (int n = 0; n < 4; n++) {
        const __half* row = qkv + (size_t)t[n] * (3 * HDIM) + head * HEADDIM + 2 * lane;
        q[n] = __half22float2(*(const __half2*)&row[0]);
        k[n] = __half22float2(*(const __half2*)&row[HDIM]);
        v[n] = __half22float2(*(const __half2*)&row[2 * HDIM]);
    }

    float s[4][4];
#pragma unroll
    for (int n = 0; n < 4; n++)
#pragma unroll
        for (int m = 0; m < 4; m++) s[n][m] = q[n].x * k[m].x + q[n].y * k[m].y;

#pragma unroll
    for (int o = 16; o > 0; o >>= 1)
#pragma unroll
        for (int n = 0; n < 4; n++)
#pragma unroll
            for (int m = 0; m < 4; m++) s[n][m] += __shfl_xor_sync(0xffffffffu, s[n][m], o);

#pragma unroll
    for (int n = 0; n < 4; n++) {
        float p[4], l = 0.f;
#pragma unroll
        for (int m = 0; m < 4; m++) { p[m] = __expf(s[n][m] * SCALE); l += p[m]; }
        float inv = 1.f / l;
        float ox = 0.f, oy = 0.f;
#pragma unroll
        for (int m = 0; m < 4; m++) { ox += p[m] * v[m].x; oy += p[m] * v[m].y; }
        *(__half2*)&hout[(size_t)t[n] * HDIM + head * HEADDIM + 2 * lane] =
            __floats2half2_rn(ox * inv, oy * inv);
    }
}

// ---------------- low-freq flash attention: ex2.f16x2 + ones-mma row sums ----
#define LQH 0
#define LKH 9216
#define LVH 18432
#define LPH 27648
#define KVSTG 4608
#define LA_SMEM 73728
#define ONES_H2 0x3C003C00u

__global__ void __launch_bounds__(256, 2) lowattn_h16_kernel(const __half* __restrict__ lq,
                                                             const __half* __restrict__ kv,
                                                             __half* __restrict__ lo) {
    extern __shared__ char smc[];
    const uint32_t smb = smem_u32(smc);
    uint32_t* smu = (uint32_t*)smc;

    int q0 = blockIdx.x * 128;
    int bh = blockIdx.y;
    int b = bh >> 2, head = bh & 3;
    int tid = threadIdx.x;
    int warp = tid >> 5, lane = tid & 31;
    int g = lane >> 2, tig = lane & 3;
    int rbase = warp * 16;

    auto fill_kv = [&](int chunk) {
        int s = chunk & 1;
        uint32_t kb = smb + (LKH + s * KVSTG) * 2;
        uint32_t vb = smb + (LVH + s * KVSTG) * 2;
#pragma unroll
        for (int i = 0; i < 2; i++) {
            int id = tid + i * 256;
            int r = id >> 3, c = (id & 7) * 8;
            const __half* src = kv + (size_t)(b * GWIN + chunk * 64 + r) * (2 * LDIM)
                                + head * HEADDIM + c;
            cp16(kb + (r * 72 + c) * 2, src);
            cp16(vb + (r * 72 + c) * 2, src + LDIM);
        }
    };

    {
        uint32_t qb = smb + LQH * 2;
#pragma unroll
        for (int i = 0; i < 4; i++) {
            int id = tid + i * 256;
            int r = id >> 3, c = (id & 7) * 8;
            cp16(qb + (r * 72 + c) * 2,
                 &lq[(size_t)(b * HW + q0 + r) * LDIM + head * HEADDIM + c]);
        }
        fill_kv(0);
        CP_COMMIT();
    }

    float O[8][4];
#pragma unroll
    for (int nt = 0; nt < 8; nt++)
#pragma unroll
        for (int j = 0; j < 4; j++) O[nt][j] = 0.f;
    float Lacc[4] = {0.f, 0.f, 0.f, 0.f};   // ones-mma row sums
    const uint32_t ones_bf[2] = { ONES_H2, ONES_H2 };

    uint32_t af_q[4][4];   // Q fragments, loaded once at t==0

    for (int t = 0; t < 16; t++) {
        if (t + 1 < 16) fill_kv(t + 1);
        CP_COMMIT();
        CP_WAIT(1);
        __syncthreads();
        int s = t & 1;
        uint32_t kbase = smb + (LKH + s * KVSTG) * 2;
        uint32_t vbase = smb + (LVH + s * KVSTG) * 2;
        uint32_t pbase = smb + LPH * 2;

        if (t == 0) {
            uint32_t qbase = smb + LQH * 2;
#pragma unroll
            for (int ks = 0; ks < 4; ks++)
                ldsm4(af_q[ks],
                      qbase + ((rbase + (lane & 15)) * 72 + ks * 16 + (lane >> 4) * 8) * 2);
        }

        float S[8][4];
#pragma unroll
        for (int nt = 0; nt < 8; nt++)
#pragma unroll
            for (int j = 0; j < 4; j++) S[nt][j] = 0.f;

#pragma unroll
        for (int ks = 0; ks < 4; ks++) {
#pragma unroll
            for (int np = 0; np < 4; np++) {
                uint32_t r4[4];
                uint32_t addr = kbase +
                    ((np * 16 + (lane & 7) + (lane >> 4) * 8) * 72 +
                     ks * 16 + ((lane >> 3) & 1) * 8) * 2;
                ldsm4(r4, addr);
                uint32_t bf0[2] = { r4[0], r4[1] };
                uint32_t bf1[2] = { r4[2], r4[3] };
                mma_f16(S[2 * np], af_q[ks], bf0);
                mma_f16(S[2 * np + 1], af_q[ks], bf1);
            }
        }

        // P = 2^(S * SCALE * log2e) via one MUFU per two values; store as half2
        int r = rbase + g;
#pragma unroll
        for (int nt = 0; nt < 8; nt++) {
            smu[(LPH >> 1) + r * 36 + nt * 4 + tig] =
                exp2h2(S[nt][0] * SCALE_LOG2E, S[nt][1] * SCALE_LOG2E);
            smu[(LPH >> 1) + (r + 8) * 36 + nt * 4 + tig] =
                exp2h2(S[nt][2] * SCALE_LOG2E, S[nt][3] * SCALE_LOG2E);
        }
        __syncwarp();

        // O += P @ V ; L += P @ ones (row sums on the tensor pipe)
#pragma unroll
        for (int ks = 0; ks < 4; ks++) {
            uint32_t af[4];
            ldsm4(af, pbase + ((rbase + (lane & 15)) * 72 + ks * 16 + (lane >> 4) * 8) * 2);
            mma_f16(Lacc, af, ones_bf);
#pragma unroll
            for (int np = 0; np < 4; np++) {
                uint32_t r4[4];
                uint32_t addr = vbase +
                    ((ks * 16 + (lane & 15)) * 72 + np * 16 + (lane >> 4) * 8) * 2;
                ldsm4t(r4, addr);
                uint32_t bf0[2] = { r4[0], r4[1] };
                uint32_t bf1[2] = { r4[2], r4[3] };
                mma_f16(O[2 * np], af, bf0);
                mma_f16(O[2 * np + 1], af, bf1);
            }
        }
        __syncthreads();
    }

    float inv0 = 1.f / Lacc[0], inv1 = 1.f / Lacc[2];
    int r = q0 + rbase + g;
#pragma unroll
    for (int nt = 0; nt < 8; nt++) {
        int c = head * HEADDIM + nt * 8 + tig * 2;
        *(uint32_t*)&lo[(size_t)(b * HW + r) * LDIM + c] = packh2(O[nt][0] * inv0, O[nt][1] * inv0);
        *(uint32_t*)&lo[(size_t)(b * HW + r + 8) * LDIM + c] = packh2(O[nt][2] * inv1, O[nt][3] * inv1);
    }
}

// ---------------- launch ----------------
extern "C" void kernel_launch(void* const* d_in, const int* in_sizes, int n_in,
                              void* d_out, int out_size) {
    const float* x        = (const float*)d_in[0];
    const float* h_qkv_w  = (const float*)d_in[1];
    const float* h_proj_w = (const float*)d_in[2];
    const float* h_proj_b = (const float*)d_in[3];
    const float* l_q_w    = (const float*)d_in[4];
    const float* l_kv_w   = (const float*)d_in[5];
    const float* l_proj_w = (const float*)d_in[6];
    const float* l_proj_b = (const float*)d_in[7];
    float* out = (float*)d_out;

    __half *p_xt, *p_pooled, *p_wt, *p_qkv, *p_hout, *p_lq, *p_kv, *p_lo;
    cudaGetSymbolAddress((void**)&p_xt, g_xt);
    cudaGetSymbolAddress((void**)&p_pooled, g_pooled);
    cudaGetSymbolAddress((void**)&p_wt, g_wt);
    cudaGetSymbolAddress((void**)&p_qkv, g_qkv);
    cudaGetSymbolAddress((void**)&p_hout, g_hout);
    cudaGetSymbolAddress((void**)&p_lq, g_lq);
    cudaGetSymbolAddress((void**)&p_kv, g_kv);
    cudaGetSymbolAddress((void**)&p_lo, g_lo);

    cudaFuncSetAttribute(h16_gemm_mega,
                         cudaFuncAttributeMaxDynamicSharedMemorySize, H16_SMEM);
    cudaFuncSetAttribute(h16_gemm_proj,
                         cudaFuncAttributeMaxDynamicSharedMemorySize, H16_SMEM);
    cudaFuncSetAttribute(lowattn_h16_kernel,
                         cudaFuncAttributeMaxDynamicSharedMemorySize, LA_SMEM);

    // 0) layout prep
    transpose_x_kernel<<<dim3(HW / 32, CDIM / 32, BATCH), dim3(32, 8)>>>(x, p_xt);
    wtrans_all_kernel<<<896, dim3(32, 8)>>>(h_qkv_w, l_q_w, l_kv_w, h_proj_w, l_proj_w, p_wt);
    // 1) pool
    pool_kernel<<<BATCH * GWIN, 128>>>(p_xt, p_pooled);
    // 2) MEGA: [qkv|lq] (1024 blocks) + kv (128 blocks)
    h16_gemm_mega<<<1152, 256, H16_SMEM>>>();
    // 3) window attention
    winattn_kernel<<<BATCH * GWIN / 2, 256>>>(p_qkv, p_hout);
    // 4) low-freq flash attention
    lowattn_h16_kernel<<<dim3(HW / 128, BATCH * 4), 256, LA_SMEM>>>(p_lq, p_kv, p_lo);
    // 5) fused projections
    h16_gemm_proj<<<dim3(HDIM / 128, TTOK / 128, 2), 256, H16_SMEM>>>(h_proj_b, l_proj_b, out);
}